// round 4
// baseline (speedup 1.0000x reference)
#include <cuda_runtime.h>
#include <math.h>

#define NB      2
#define NPTS    6144
#define DIM     32
#define R2      0.0009f
#define TH      0.7f
#define JSPLIT  8
#define ITILE   32
#define PSTRIDE 35               // odd stride -> conflict-free partial buffer
#define HSTRIDE 33               // odd stride -> conflict-free h buffer
#define G       10               // grid cells per axis (cell size == radius)
#define NCELL   1000
#define CSZ     0.03f
#define INVC    33.333332f       // 1/0.03
#define NCHUNK  32
#define CHUNK   192              // NPTS / NCHUNK
#define NHH     (NB * NCHUNK * NCELL)

// Scratch (device globals; no allocation anywhere)
__device__ float  g_norm[NB * NPTS];            // clamped embedding norms
__device__ float4 g_pln[NB * NPTS];             // compacted leaf: x,y,z,norm (unsorted)
__device__ int    g_listu[NB * NPTS];           // compacted leaf: original local idx
__device__ int    g_cell[NB * NPTS];            // compacted leaf: cell id
__device__ int    g_cnt[NB];                    // leaf count per batch
__device__ int    g_hh[NHH];                    // per-chunk per-cell histogram
__device__ int    g_cstart[NB * 1024];          // cell exclusive prefix; [1000] = cnt
__device__ float4 g_spln[NB * NPTS];            // cell-sorted leaf pos+norm
__device__ int    g_slist[NB * NPTS];           // cell-sorted original idx
__device__ float  g_semb[NB * NPTS * DIM];      // cell-sorted leaf embeddings

// ---------------------------------------------------------------------------
// Prep: copy embeddings -> out, compute clamped norms, zero histogram
// ---------------------------------------------------------------------------
__global__ void prep_kernel(const float* __restrict__ emb,
                            float*       __restrict__ out) {
    const int idx = blockIdx.x * 256 + threadIdx.x;
    if (idx >= NB * NPTS) return;

    // zero histogram (runs before compact_kernel on the same stream)
    for (int h = idx; h < NHH; h += NB * NPTS) g_hh[h] = 0;

    const float4* e4 = (const float4*)(emb + (size_t)idx * DIM);
    float4*       o4 = (float4*)(out + (size_t)idx * DIM);
    float s = 0.f;
#pragma unroll
    for (int k = 0; k < 8; k++) {
        float4 v = __ldg(e4 + k);
        o4[k] = v;
        s += v.x * v.x + v.y * v.y + v.z * v.z + v.w * v.w;
    }
    g_norm[idx] = fmaxf(sqrtf(s), 1e-8f);   // matches reference enorm clamp
}

// ---------------------------------------------------------------------------
// Ordered leaf compaction (ascending idx, deterministic) + cell id + histogram
// ---------------------------------------------------------------------------
__global__ void compact_kernel(const float* __restrict__ points,
                               const int*   __restrict__ leaf) {
    const int b = blockIdx.x;
    const int t = threadIdx.x;
    const int lane = t & 31;
    const int w    = t >> 5;

    __shared__ int s_base;
    __shared__ int s_wsum[8];
    if (t == 0) s_base = 0;
    __syncthreads();

    for (int c = 0; c < NPTS / 256; c++) {
        const int idx = c * 256 + t;
        const bool lf = leaf[b * NPTS + idx] > 0;
        const unsigned bal = __ballot_sync(0xFFFFFFFFu, lf);
        const int rank = __popc(bal & ((1u << lane) - 1u));
        if (lane == 0) s_wsum[w] = __popc(bal);
        __syncthreads();
        int woff = 0;
#pragma unroll
        for (int k = 0; k < 8; k++) woff += (k < w) ? s_wsum[k] : 0;
        int chunk_total = 0;
#pragma unroll
        for (int k = 0; k < 8; k++) chunk_total += s_wsum[k];
        if (lf) {
            const int p = s_base + woff + rank;
            const float px = points[(b * NPTS + idx) * 3 + 0];
            const float py = points[(b * NPTS + idx) * 3 + 1];
            const float pz = points[(b * NPTS + idx) * 3 + 2];
            g_listu[b * NPTS + p] = idx;
            g_pln[b * NPTS + p]   = make_float4(px, py, pz, g_norm[b * NPTS + idx]);
            const int cx = min(G - 1, max(0, (int)(px * INVC)));
            const int cy = min(G - 1, max(0, (int)(py * INVC)));
            const int cz = min(G - 1, max(0, (int)(pz * INVC)));
            const int cell = (cx * G + cy) * G + cz;
            g_cell[b * NPTS + p] = cell;
            atomicAdd(&g_hh[(b * NCHUNK + (p / CHUNK)) * NCELL + cell], 1);
        }
        __syncthreads();
        if (t == 0) s_base += chunk_total;
        __syncthreads();
    }
    if (t == 0) g_cnt[b] = s_base;
}

// ---------------------------------------------------------------------------
// Per-batch exclusive prefix over cell totals -> g_cstart
// 256 threads, 4 consecutive cells each (1024 padded)
// ---------------------------------------------------------------------------
__global__ void scan_kernel() {
    const int b = blockIdx.x;
    const int t = threadIdx.x;
    const int lane = t & 31;
    const int w    = t >> 5;
    __shared__ int s_w[8];

    const int c0 = t * 4;
    int loc[4];
    int s = 0;
#pragma unroll
    for (int r = 0; r < 4; r++) {
        const int c = c0 + r;
        int tot = 0;
        if (c < NCELL) {
#pragma unroll
            for (int k = 0; k < NCHUNK; k++)
                tot += g_hh[(b * NCHUNK + k) * NCELL + c];
        }
        loc[r] = s;
        s += tot;
    }
    // inclusive warp scan of per-thread sums
    int x = s;
#pragma unroll
    for (int d = 1; d < 32; d <<= 1) {
        int y = __shfl_up_sync(0xFFFFFFFFu, x, d);
        if (lane >= d) x += y;
    }
    const int pre = x - s;          // exclusive within warp
    if (lane == 31) s_w[w] = x;     // warp total
    __syncthreads();
    if (t == 0) {
        int acc = 0;
#pragma unroll
        for (int i = 0; i < 8; i++) { int y = s_w[i]; s_w[i] = acc; acc += y; }
        g_cstart[b * 1024 + NCELL] = acc;   // == cnt
    }
    __syncthreads();
    const int base = s_w[w] + pre;
#pragma unroll
    for (int r = 0; r < 4; r++) {
        const int c = c0 + r;
        if (c < NCELL) g_cstart[b * 1024 + c] = base + loc[r];
    }
}

// ---------------------------------------------------------------------------
// Stable placement: thread (cell c, chunk k) scans its chunk in ascending order
// and writes matches at cstart[c] + (counts of c in earlier chunks). Deterministic.
// ---------------------------------------------------------------------------
__global__ void place_kernel() {
    const int b   = blockIdx.y;
    const int tid = blockIdx.x * 256 + threadIdx.x;   // gridDim.x = 128 -> 32768
    const int k   = tid >> 10;                        // 0..31
    const int c   = tid & 1023;
    if (c >= NCELL) return;

    const int cnt = g_cnt[b];
    int base = g_cstart[b * 1024 + c];
    for (int kk = 0; kk < k; kk++)
        base += g_hh[(b * NCHUNK + kk) * NCELL + c];

    const int jb = k * CHUNK;
    const int je = min(jb + CHUNK, cnt);
    for (int j = jb; j < je; j++) {
        if (__ldg(&g_cell[b * NPTS + j]) == c) {      // uniform load across warp
            g_spln[b * NPTS + base]  = g_pln[b * NPTS + j];
            g_slist[b * NPTS + base] = g_listu[b * NPTS + j];
            base++;
        }
    }
}

// ---------------------------------------------------------------------------
// Gather cell-sorted leaf embeddings (dense, coalesced)
// ---------------------------------------------------------------------------
__global__ void gather_kernel(const float* __restrict__ emb) {
    int tid = blockIdx.x * 256 + threadIdx.x;          // over NB*NPTS*8 float4
    if (tid >= NB * NPTS * 8) return;
    const int b = tid / (NPTS * 8);
    const int r = tid - b * (NPTS * 8);
    const int p = r >> 3;
    const int k = r & 7;
    if (p >= g_cnt[b]) return;
    const int j = g_slist[b * NPTS + p];
    const float4 v = __ldg((const float4*)(emb + ((size_t)b * NPTS + j) * DIM) + k);
    ((float4*)(g_semb + ((size_t)b * NPTS + p) * DIM))[k] = v;
}

// ---------------------------------------------------------------------------
// Main: per sorted-leaf-i tile, grid-windowed neighbor scan + fused MLP
// Thread layout: t = sub*32 + il;  lane il = i within tile, warp sub = j-stripe
// ---------------------------------------------------------------------------
__global__ __launch_bounds__(256, 2)
void main_kernel(const float* __restrict__ W1,
                 const float* __restrict__ b1,
                 const float* __restrict__ W2,
                 const float* __restrict__ b2,
                 float*       __restrict__ out) {
    __shared__ float s_part[256 * PSTRIDE];  // partials; later reused for h
    __shared__ float s_W1[64 * DIM];
    __shared__ float s_W2[DIM * DIM];
    __shared__ float s_b1[DIM];
    __shared__ float s_b2[DIM];

    const int t   = threadIdx.x;
    const int il  = t & 31;
    const int sub = t >> 5;
    const int b   = blockIdx.y;

    const int cnt = g_cnt[b];
    if (cnt < 10) return;                      // batch early-exit: out stays = embeddings
    if (blockIdx.x * ITILE >= cnt) return;     // uniform per block

    // Cooperative weight staging
#pragma unroll
    for (int k = 0; k < 8; k++) s_W1[t + 256 * k] = W1[t + 256 * k];
#pragma unroll
    for (int k = 0; k < 4; k++) s_W2[t + 256 * k] = W2[t + 256 * k];
    if (t < DIM) { s_b1[t] = b1[t]; s_b2[t] = b2[t]; }

    const int  li     = blockIdx.x * ITILE + il;
    const bool active = li < cnt;
    const int  lis    = active ? li : (cnt - 1);   // duplicate a nearby valid point

    const float* LE = g_semb + (size_t)b * NPTS * DIM;

    float ei[DIM];
    {
        const float4* ei4 = (const float4*)(LE + (size_t)lis * DIM);
#pragma unroll
        for (int k = 0; k < 8; k++) {
            float4 v = __ldg(ei4 + k);
            ei[4 * k + 0] = v.x; ei[4 * k + 1] = v.y;
            ei[4 * k + 2] = v.z; ei[4 * k + 3] = v.w;
        }
    }
    const float4 qi = g_spln[b * NPTS + lis];
    const float xi = qi.x, yi = qi.y, zi = qi.z, normi = qi.w;

    // Tile bbox via warp shfl reduction (identical in every warp: same il->li map)
    float xmn = xi, xmx = xi, ymn = yi, ymx = yi, zmn = zi, zmx = zi;
#pragma unroll
    for (int d = 16; d; d >>= 1) {
        xmn = fminf(xmn, __shfl_xor_sync(0xFFFFFFFFu, xmn, d));
        xmx = fmaxf(xmx, __shfl_xor_sync(0xFFFFFFFFu, xmx, d));
        ymn = fminf(ymn, __shfl_xor_sync(0xFFFFFFFFu, ymn, d));
        ymx = fmaxf(ymx, __shfl_xor_sync(0xFFFFFFFFu, ymx, d));
        zmn = fminf(zmn, __shfl_xor_sync(0xFFFFFFFFu, zmn, d));
        zmx = fmaxf(zmx, __shfl_xor_sync(0xFFFFFFFFu, zmx, d));
    }
    const float pad = CSZ * 1.0001f;           // radius + fp-boundary margin
    const int cx0 = max(0, (int)floorf((xmn - pad) * INVC));
    const int cx1 = min(G - 1, (int)floorf((xmx + pad) * INVC));
    const int cy0 = max(0, (int)floorf((ymn - pad) * INVC));
    const int cy1 = min(G - 1, (int)floorf((ymx + pad) * INVC));
    const int cz0 = max(0, (int)floorf((zmn - pad) * INVC));
    const int cz1 = min(G - 1, (int)floorf((zmx + pad) * INVC));

    float ssum[DIM];
#pragma unroll
    for (int k = 0; k < DIM; k++) ssum[k] = 0.f;
    int cnb = 0, csim = 0;

    const float4* pl = g_spln + b * NPTS;
    const int*    cs = g_cstart + b * 1024;

    for (int cx = cx0; cx <= cx1; cx++) {
        for (int cy = cy0; cy <= cy1; cy++) {
            const int row = (cx * G + cy) * G;
            const int jb = __ldg(cs + row + cz0);
            const int je = __ldg(cs + row + cz1 + 1);   // contiguous z-run
            for (int j = jb + sub; j < je; j += JSPLIT) {
                float4 q  = __ldg(pl + j);              // uniform across warp
                float dx = q.x - xi, dy = q.y - yi, dz = q.z - zi;
                float d2 = fmaf(dx, dx, fmaf(dy, dy, dz * dz));
                if (d2 < R2 && active) {
                    cnb++;
                    const float4* ej4 = (const float4*)(LE + (size_t)j * DIM);
                    float dot = 0.f;
#pragma unroll
                    for (int k = 0; k < 8; k++) {
                        float4 v = __ldg(ej4 + k);
                        dot = fmaf(ei[4 * k + 0], v.x, dot);
                        dot = fmaf(ei[4 * k + 1], v.y, dot);
                        dot = fmaf(ei[4 * k + 2], v.z, dot);
                        dot = fmaf(ei[4 * k + 3], v.w, dot);
                    }
                    float sim = dot / (normi * q.w);    // same op shape as reference
                    if (sim > TH) {
                        csim++;
#pragma unroll
                        for (int k = 0; k < 8; k++) {   // reload (L1-hot), keeps regs low
                            float4 v = __ldg(ej4 + k);
                            ssum[4 * k + 0] += v.x;
                            ssum[4 * k + 1] += v.y;
                            ssum[4 * k + 2] += v.z;
                            ssum[4 * k + 3] += v.w;
                        }
                    }
                }
            }
        }
    }

    // Write per-sub partials (inactive lanes wrote zeros)
    {
        float* pp = s_part + (sub * 32 + il) * PSTRIDE;
#pragma unroll
        for (int k = 0; k < DIM; k++) pp[k] = ssum[k];
        pp[32] = (float)cnb;
        pp[33] = (float)csim;
    }
    __syncthreads();

    // Every thread reduces its lane-i's 8 partials in fixed order (deterministic)
    float msum[DIM];
#pragma unroll
    for (int k = 0; k < DIM; k++) msum[k] = 0.f;
    float fcnb = 0.f, fcsim = 0.f;
#pragma unroll
    for (int s = 0; s < JSPLIT; s++) {
        const float* q = s_part + (s * 32 + il) * PSTRIDE;
#pragma unroll
        for (int k = 0; k < DIM; k++) msum[k] += q[k];
        fcnb  += q[32];
        fcsim += q[33];
    }
    const int  tot_nb  = (int)fcnb;
    const int  tot_sim = (int)fcsim;
    const bool cond    = (tot_nb > 1) && (tot_sim > 0);
    const float denom  = (float)max(tot_sim, 1);

    float mean_[DIM];
#pragma unroll
    for (int k = 0; k < DIM; k++) mean_[k] = msum[k] / denom;  // IEEE div like reference

    __syncthreads();   // all partial reads done before s_part is reused for h

    // Layer 1: thread (il, sub) computes h[d0..d0+3], d0 = sub*4
    const int d0 = sub * 4;
    float h[4];
#pragma unroll
    for (int r = 0; r < 4; r++) h[r] = s_b1[d0 + r];
#pragma unroll
    for (int k = 0; k < DIM; k++) {
        float c = ei[k];
#pragma unroll
        for (int r = 0; r < 4; r++) h[r] = fmaf(c, s_W1[k * DIM + d0 + r], h[r]);
    }
#pragma unroll
    for (int k = 0; k < DIM; k++) {
        float c = mean_[k];
#pragma unroll
        for (int r = 0; r < 4; r++) h[r] = fmaf(c, s_W1[(DIM + k) * DIM + d0 + r], h[r]);
    }
    {
        float* hrow = s_part + il * HSTRIDE;   // reuse, padded stride
#pragma unroll
        for (int r = 0; r < 4; r++) hrow[d0 + r] = fmaxf(h[r], 0.f);
    }
    __syncthreads();

    // Layer 2
    float o[4];
#pragma unroll
    for (int r = 0; r < 4; r++) o[r] = s_b2[d0 + r];
    {
        const float* hrow = s_part + il * HSTRIDE;
#pragma unroll
        for (int k = 0; k < DIM; k++) {
            float c = hrow[k];
#pragma unroll
            for (int r = 0; r < 4; r++) o[r] = fmaf(c, s_W2[k * DIM + d0 + r], o[r]);
        }
    }

    if (active && cond) {
        const int i = g_slist[b * NPTS + li];   // original row for output
        float4* op = (float4*)(out + ((size_t)b * NPTS + i) * DIM + d0);
        *op = make_float4(o[0], o[1], o[2], o[3]);
    }
}

// ---------------------------------------------------------------------------
extern "C" void kernel_launch(void* const* d_in, const int* in_sizes, int n_in,
                              void* d_out, int out_size) {
    const float* points = (const float*)d_in[0];
    const float* emb    = (const float*)d_in[1];
    const int*   leaf   = (const int*)d_in[2];
    const float* W1     = (const float*)d_in[3];
    const float* b1     = (const float*)d_in[4];
    const float* W2     = (const float*)d_in[5];
    const float* b2     = (const float*)d_in[6];
    float*       out    = (float*)d_out;

    prep_kernel<<<(NB * NPTS + 255) / 256, 256>>>(emb, out);
    compact_kernel<<<NB, 256>>>(points, leaf);
    scan_kernel<<<NB, 256>>>();
    place_kernel<<<dim3(128, NB), 256>>>();
    gather_kernel<<<(NB * NPTS * 8 + 255) / 256, 256>>>(emb);

    dim3 grid(NPTS / ITILE, NB);   // worst-case tiles; surplus blocks exit instantly
    main_kernel<<<grid, 256>>>(W1, b1, W2, b2, out);
}

// round 10
// speedup vs baseline: 1.4106x; 1.4106x over previous
#include <cuda_runtime.h>
#include <math.h>

#define NB      2
#define NPTS    6144
#define DIM     32
#define R2      0.0009f
#define TH      0.7f
#define JSPLIT  8
#define ITILE   32
#define PSTRIDE 35               // odd stride -> conflict-free partial buffer
#define HSTRIDE 33               // odd stride -> conflict-free h buffer
#define G       10               // grid cells per axis (cell size == radius)
#define NCELL   1000
#define CSZ     0.03f
#define INVC    33.333332f       // 1/0.03
#define NCHUNK  24               // chunks of 256 (one block) per batch
#define NHH     (NB * NCHUNK * NCELL)

// Scratch (device globals; no allocation anywhere; all fully rewritten per run)
__device__ float4 g_pln4[NB * NPTS];            // per original idx: x,y,z,norm
__device__ int    g_cell[NB * NPTS];            // per original idx: cell or -1
__device__ int    g_rank[NB * NPTS];            // stable rank within (chunk, cell)
__device__ int    g_hh[NHH];                    // per-chunk per-cell counts (dense overwrite)
__device__ int    g_base[NHH];                  // per-chunk per-cell dest base
__device__ int    g_cstart[NB * 1024];          // cell exclusive prefix; [1000] = leaf cnt
__device__ float4 g_spln[NB * NPTS];            // cell-sorted leaf pos+norm
__device__ int    g_slist[NB * NPTS];           // cell-sorted original local idx
__device__ float4 g_semb[NB * NPTS * 8];        // cell-sorted leaf embeddings (8 float4/row)

// ---------------------------------------------------------------------------
// A: copy embeddings -> out, norms, cell ids, stable in-chunk ranks,
//    dense per-chunk cell counts (no atomics, no pre-zero invariants).
//    One block == one chunk of 256 original indices.
// ---------------------------------------------------------------------------
__global__ __launch_bounds__(256)
void prep_kernel(const float* __restrict__ points,
                 const float* __restrict__ emb,
                 const int*   __restrict__ leaf,
                 float*       __restrict__ out) {
    __shared__ int s_cnt[NCELL];

    const int t   = threadIdx.x;
    const int lane = t & 31;
    const int w    = t >> 5;
    const int idx  = blockIdx.x * 256 + t;        // 48 blocks -> b*NPTS + k*256 + t

    for (int c = t; c < NCELL; c += 256) s_cnt[c] = 0;

    // embedding copy + norm (independent of ranking; overlaps the sync rounds)
    const float4* e4 = (const float4*)(emb + (size_t)idx * DIM);
    float4*       o4 = (float4*)(out + (size_t)idx * DIM);
    float s = 0.f;
#pragma unroll
    for (int k = 0; k < 8; k++) {
        float4 v = __ldg(e4 + k);
        o4[k] = v;
        s += v.x * v.x + v.y * v.y + v.z * v.z + v.w * v.w;
    }
    const float nrm = fmaxf(sqrtf(s), 1e-8f);     // matches reference enorm clamp

    const float px = points[idx * 3 + 0];
    const float py = points[idx * 3 + 1];
    const float pz = points[idx * 3 + 2];
    g_pln4[idx] = make_float4(px, py, pz, nrm);

    int cell = -1;
    if (leaf[idx] > 0) {
        const int cx = min(G - 1, max(0, (int)(px * INVC)));
        const int cy = min(G - 1, max(0, (int)(py * INVC)));
        const int cz = min(G - 1, max(0, (int)(pz * INVC)));
        cell = (cx * G + cy) * G + cz;
    }
    g_cell[idx] = cell;
    __syncthreads();

    // Stable block-wide rank per cell: warps serialized in fixed order.
    int rank = 0;
#pragma unroll 1
    for (int r = 0; r < 8; r++) {
        if (w == r) {
            const unsigned peers = __match_any_sync(0xFFFFFFFFu, cell);
            const int wrank  = __popc(peers & ((1u << lane) - 1u));
            const int wcnt   = __popc(peers);
            const int leader = __ffs(peers) - 1;
            int base = 0;
            if (cell >= 0 && lane == leader) base = s_cnt[cell];
            base = __shfl_sync(0xFFFFFFFFu, base, leader);
            if (cell >= 0) {
                rank = base + wrank;
                if (lane == leader) s_cnt[cell] = base + wcnt;
            }
        }
        __syncthreads();
    }
    g_rank[idx] = rank;

    // dense per-chunk counts (zeros included -> fully overwritten every run)
    for (int c = t; c < NCELL; c += 256)
        g_hh[blockIdx.x * NCELL + c] = s_cnt[c];
}

// ---------------------------------------------------------------------------
// B: per batch (1 block, 1024 thr): cell totals -> block scan -> cstart,
//    then per-(chunk,cell) destination bases. NCHUNK=24 keeps traffic tiny.
// ---------------------------------------------------------------------------
__global__ __launch_bounds__(1024)
void scan_kernel() {
    const int b = blockIdx.x;
    const int t = threadIdx.x;
    const int lane = t & 31;
    const int w    = t >> 5;
    __shared__ int s_w[32];

    int hv[NCHUNK];
    int tot = 0;
    if (t < NCELL) {
#pragma unroll
        for (int k = 0; k < NCHUNK; k++) {
            hv[k] = g_hh[(b * NCHUNK + k) * NCELL + t];
            tot += hv[k];
        }
    }
    // block-wide exclusive scan of tot (1024 threads; t>=NCELL contribute 0)
    int x = tot;
#pragma unroll
    for (int d = 1; d < 32; d <<= 1) {
        int y = __shfl_up_sync(0xFFFFFFFFu, x, d);
        if (lane >= d) x += y;
    }
    if (lane == 31) s_w[w] = x;
    __syncthreads();
    if (w == 0) {
        int v = s_w[lane];
        int y = v;
#pragma unroll
        for (int d = 1; d < 32; d <<= 1) {
            int z = __shfl_up_sync(0xFFFFFFFFu, y, d);
            if (lane >= d) y += z;
        }
        s_w[lane] = y - v;   // exclusive warp prefix
    }
    __syncthreads();
    const int base = s_w[w] + (x - tot);   // exclusive prefix for this thread

    if (t < NCELL) g_cstart[b * 1024 + t] = base;
    if (t == 1023) g_cstart[b * 1024 + NCELL] = base;   // == total leaf count

    if (t < NCELL) {
        int acc = base;
#pragma unroll
        for (int k = 0; k < NCHUNK; k++) {
            g_base[(b * NCHUNK + k) * NCELL + t] = acc;
            acc += hv[k];
        }
    }
}

// ---------------------------------------------------------------------------
// C: trivial scatter: dest = base[chunk][cell] + rank. Fused embedding gather.
// ---------------------------------------------------------------------------
__global__ __launch_bounds__(256)
void place_kernel(const float* __restrict__ emb) {
    const int idx = blockIdx.x * 256 + threadIdx.x;    // 48 blocks -> 12288
    const int cell = __ldg(&g_cell[idx]);
    if (cell < 0) return;
    const int b = blockIdx.x / NCHUNK;                 // chunk == block
    const int k = blockIdx.x - b * NCHUNK;
    const int l = k * 256 + threadIdx.x;               // local original index

    const int dest = __ldg(&g_base[blockIdx.x * NCELL + cell]) + __ldg(&g_rank[idx]);
    g_spln[b * NPTS + dest]  = g_pln4[idx];
    g_slist[b * NPTS + dest] = l;
    const float4* src = (const float4*)(emb + (size_t)idx * DIM);
    float4*       dst = g_semb + (size_t)(b * NPTS + dest) * 8;
#pragma unroll
    for (int q = 0; q < 8; q++) dst[q] = __ldg(src + q);
}

// ---------------------------------------------------------------------------
// D: per sorted-leaf-i tile, grid-windowed neighbor scan + fused MLP
// Thread layout: t = sub*32 + il;  lane il = i within tile, warp sub = j-stripe
// ---------------------------------------------------------------------------
__global__ __launch_bounds__(256, 2)
void main_kernel(const float* __restrict__ W1,
                 const float* __restrict__ b1,
                 const float* __restrict__ W2,
                 const float* __restrict__ b2,
                 float*       __restrict__ out) {
    __shared__ __align__(16) float s_part[256 * PSTRIDE];  // partials; later reused for h
    __shared__ __align__(16) float s_W1[64 * DIM];
    __shared__ __align__(16) float s_W2[DIM * DIM];
    __shared__ float s_b1[DIM];
    __shared__ float s_b2[DIM];

    const int t   = threadIdx.x;
    const int il  = t & 31;
    const int sub = t >> 5;
    const int b   = blockIdx.y;

    const int cnt = g_cstart[b * 1024 + NCELL];
    if (cnt < 10) return;                      // batch early-exit: out stays = embeddings
    if (blockIdx.x * ITILE >= cnt) return;     // uniform per block

    // Cooperative weight staging (vectorized float4)
    {
        const float4* w1v = (const float4*)W1;
        float4*       s1v = (float4*)s_W1;
#pragma unroll
        for (int k = 0; k < 2; k++) s1v[t + 256 * k] = __ldg(w1v + t + 256 * k);
        const float4* w2v = (const float4*)W2;
        float4*       s2v = (float4*)s_W2;
        s2v[t] = __ldg(w2v + t);
        if (t < DIM) { s_b1[t] = b1[t]; s_b2[t] = b2[t]; }
    }

    const int  li     = blockIdx.x * ITILE + il;
    const bool active = li < cnt;
    const int  lis    = active ? li : (cnt - 1);   // duplicate a nearby valid point

    const float4* LE = g_semb + (size_t)b * NPTS * 8;

    float ei[DIM];
    {
        const float4* ei4 = LE + (size_t)lis * 8;
#pragma unroll
        for (int k = 0; k < 8; k++) {
            float4 v = __ldg(ei4 + k);
            ei[4 * k + 0] = v.x; ei[4 * k + 1] = v.y;
            ei[4 * k + 2] = v.z; ei[4 * k + 3] = v.w;
        }
    }
    const float4 qi = g_spln[b * NPTS + lis];
    // bbox uses the true position; the scan predicate uses a sentinel for
    // padded lanes so `d2 < R2` is always false for them (no extra operand).
    const float xi = active ? qi.x : 1e9f;
    const float yi = qi.y, zi = qi.z, normi = qi.w;

    // Tile bbox via warp shfl reduction (identical in every warp: same il->li map)
    float xmn = qi.x, xmx = qi.x, ymn = yi, ymx = yi, zmn = zi, zmx = zi;
#pragma unroll
    for (int d = 16; d; d >>= 1) {
        xmn = fminf(xmn, __shfl_xor_sync(0xFFFFFFFFu, xmn, d));
        xmx = fmaxf(xmx, __shfl_xor_sync(0xFFFFFFFFu, xmx, d));
        ymn = fminf(ymn, __shfl_xor_sync(0xFFFFFFFFu, ymn, d));
        ymx = fmaxf(ymx, __shfl_xor_sync(0xFFFFFFFFu, ymx, d));
        zmn = fminf(zmn, __shfl_xor_sync(0xFFFFFFFFu, zmn, d));
        zmx = fmaxf(zmx, __shfl_xor_sync(0xFFFFFFFFu, zmx, d));
    }
    const float pad = CSZ * 1.0001f;           // radius + fp-boundary margin
    const int cx0 = max(0, (int)floorf((xmn - pad) * INVC));
    const int cx1 = min(G - 1, (int)floorf((xmx + pad) * INVC));
    const int cy0 = max(0, (int)floorf((ymn - pad) * INVC));
    const int cy1 = min(G - 1, (int)floorf((ymx + pad) * INVC));
    const int cz0 = max(0, (int)floorf((zmn - pad) * INVC));
    const int cz1 = min(G - 1, (int)floorf((zmx + pad) * INVC));

    float ssum[DIM];
#pragma unroll
    for (int k = 0; k < DIM; k++) ssum[k] = 0.f;
    int cnb = 0, csim = 0;

    const float4* pl = g_spln + b * NPTS;
    const int*    cs = g_cstart + b * 1024;

    for (int cx = cx0; cx <= cx1; cx++) {
        for (int cy = cy0; cy <= cy1; cy++) {
            const int row = (cx * G + cy) * G;
            const int jb = __ldg(cs + row + cz0);
            const int je = __ldg(cs + row + cz1 + 1);   // contiguous z-run
            for (int j = jb + sub; j < je; j += JSPLIT) {
                float4 q  = __ldg(pl + j);              // uniform across warp
                float dx = q.x - xi, dy = q.y - yi, dz = q.z - zi;
                float d2 = fmaf(dx, dx, fmaf(dy, dy, dz * dz));
                if (d2 < R2) {                          // padded lanes: xi=1e9 -> false
                    cnb++;
                    const float4* ej4 = LE + (size_t)j * 8;
                    float dot = 0.f;
#pragma unroll
                    for (int k = 0; k < 8; k++) {
                        float4 v = __ldg(ej4 + k);
                        dot = fmaf(ei[4 * k + 0], v.x, dot);
                        dot = fmaf(ei[4 * k + 1], v.y, dot);
                        dot = fmaf(ei[4 * k + 2], v.z, dot);
                        dot = fmaf(ei[4 * k + 3], v.w, dot);
                    }
                    float sim = dot / (normi * q.w);    // same op shape as reference
                    if (sim > TH) {
                        csim++;
#pragma unroll
                        for (int k = 0; k < 8; k++) {   // reload (L1-hot), keeps regs low
                            float4 v = __ldg(ej4 + k);
                            ssum[4 * k + 0] += v.x;
                            ssum[4 * k + 1] += v.y;
                            ssum[4 * k + 2] += v.z;
                            ssum[4 * k + 3] += v.w;
                        }
                    }
                }
            }
        }
    }

    // Write per-sub partials (inactive lanes wrote zeros)
    {
        float* pp = s_part + (sub * 32 + il) * PSTRIDE;
#pragma unroll
        for (int k = 0; k < DIM; k++) pp[k] = ssum[k];
        pp[32] = (float)cnb;
        pp[33] = (float)csim;
    }
    __syncthreads();

    // Every thread reduces its lane-i's 8 partials in fixed order (deterministic)
    float msum[DIM];
#pragma unroll
    for (int k = 0; k < DIM; k++) msum[k] = 0.f;
    float fcnb = 0.f, fcsim = 0.f;
#pragma unroll
    for (int s = 0; s < JSPLIT; s++) {
        const float* q = s_part + (s * 32 + il) * PSTRIDE;
#pragma unroll
        for (int k = 0; k < DIM; k++) msum[k] += q[k];
        fcnb  += q[32];
        fcsim += q[33];
    }
    const int  tot_nb  = (int)fcnb;
    const int  tot_sim = (int)fcsim;
    const bool cond    = (tot_nb > 1) && (tot_sim > 0);
    const float denom  = (float)max(tot_sim, 1);

    float mean_[DIM];
#pragma unroll
    for (int k = 0; k < DIM; k++) mean_[k] = msum[k] / denom;  // IEEE div like reference

    __syncthreads();   // all partial reads done before s_part is reused for h

    // Layer 1: thread (il, sub) computes h[d0..d0+3], d0 = sub*4
    const int d0 = sub * 4;
    float h[4];
#pragma unroll
    for (int r = 0; r < 4; r++) h[r] = s_b1[d0 + r];
#pragma unroll
    for (int k = 0; k < DIM; k++) {
        float c = ei[k];
#pragma unroll
        for (int r = 0; r < 4; r++) h[r] = fmaf(c, s_W1[k * DIM + d0 + r], h[r]);
    }
#pragma unroll
    for (int k = 0; k < DIM; k++) {
        float c = mean_[k];
#pragma unroll
        for (int r = 0; r < 4; r++) h[r] = fmaf(c, s_W1[(DIM + k) * DIM + d0 + r], h[r]);
    }
    {
        float* hrow = s_part + il * HSTRIDE;   // reuse, padded stride
#pragma unroll
        for (int r = 0; r < 4; r++) hrow[d0 + r] = fmaxf(h[r], 0.f);
    }
    __syncthreads();

    // Layer 2
    float o[4];
#pragma unroll
    for (int r = 0; r < 4; r++) o[r] = s_b2[d0 + r];
    {
        const float* hrow = s_part + il * HSTRIDE;
#pragma unroll
        for (int k = 0; k < DIM; k++) {
            float c = hrow[k];
#pragma unroll
            for (int r = 0; r < 4; r++) o[r] = fmaf(c, s_W2[k * DIM + d0 + r], o[r]);
        }
    }

    if (active && cond) {
        const int i = __ldg(&g_slist[b * NPTS + li]);   // original row for output
        float4* op = (float4*)(out + ((size_t)b * NPTS + i) * DIM + d0);
        *op = make_float4(o[0], o[1], o[2], o[3]);
    }
}

// ---------------------------------------------------------------------------
extern "C" void kernel_launch(void* const* d_in, const int* in_sizes, int n_in,
                              void* d_out, int out_size) {
    const float* points = (const float*)d_in[0];
    const float* emb    = (const float*)d_in[1];
    const int*   leaf   = (const int*)d_in[2];
    const float* W1     = (const float*)d_in[3];
    const float* b1     = (const float*)d_in[4];
    const float* W2     = (const float*)d_in[5];
    const float* b2     = (const float*)d_in[6];
    float*       out    = (float*)d_out;

    prep_kernel<<<NB * NCHUNK, 256>>>(points, emb, leaf, out);
    scan_kernel<<<NB, 1024>>>();
    place_kernel<<<NB * NCHUNK, 256>>>(emb);

    dim3 grid(NPTS / ITILE, NB);   // worst-case tiles; surplus blocks exit instantly
    main_kernel<<<grid, 256>>>(W1, b1, W2, b2, out);
}